// round 1
// baseline (speedup 1.0000x reference)
#include <cuda_runtime.h>
#include <math.h>

#define N_NODES 8192
#define FEAT    256
#define K1      25
#define K2      10

// Scratch (device globals — no allocation allowed)
__device__ int   g_nbr[N_NODES * K1];
__device__ int   g_cnt[N_NODES];
__device__ float g_mean[N_NODES * FEAT];
__device__ float g_h1[N_NODES * FEAT];
__device__ float g_h2[N_NODES * FEAT];

// ---------------------------------------------------------------------------
// Kernel 1: first-K1 neighbor extraction. One warp per row, ballot prefix scan
// with early exit (A is ~Bernoulli(0.5) so typically only 1-2 iterations).
// Unused neighbor slots are zero-filled so downstream loops can be predicated.
// ---------------------------------------------------------------------------
__global__ void nbr_kernel(const int* __restrict__ A) {
    int warp = (blockIdx.x * blockDim.x + threadIdx.x) >> 5;
    int lane = threadIdx.x & 31;
    if (warp >= N_NODES) return;
    const int* row = A + (size_t)warp * N_NODES;
    int found = 0;
    for (int c = 0; c < N_NODES && found < K1; c += 32) {
        int v = __ldg(row + c + lane);
        unsigned m = __ballot_sync(0xffffffffu, v > 0);
        if (v > 0) {
            int r = found + __popc(m & ((1u << lane) - 1u));
            if (r < K1) g_nbr[warp * K1 + r] = c + lane;
        }
        found += __popc(m);
    }
    int cnt = found < K1 ? found : K1;
    if (lane < K1 && lane >= cnt) g_nbr[warp * K1 + lane] = 0;  // safe dummy
    if (lane == 0) g_cnt[warp] = cnt;
}

// ---------------------------------------------------------------------------
// Kernel 2: neighbor mean over first min(cnt, K) neighbors.
// 4 nodes per 256-thread block, float4 per thread, fully unrolled + predicated.
// Input rows are L2-resident (8 MB).
// ---------------------------------------------------------------------------
template <int K, bool FROM_X>
__global__ void mean_kernel(const float* __restrict__ X) {
    const float* __restrict__ In = FROM_X ? X : (const float*)g_h1;
    int node = blockIdx.x * 4 + (threadIdx.x >> 6);
    int c4   = (threadIdx.x & 63) << 2;
    int cnt = g_cnt[node]; if (cnt > K) cnt = K;
    const int* nb = g_nbr + node * K1;
    float4 acc = make_float4(0.f, 0.f, 0.f, 0.f);
#pragma unroll
    for (int t = 0; t < K; t++) {
        if (t < cnt) {
            float4 v = *(const float4*)(In + (size_t)nb[t] * FEAT + c4);
            acc.x += v.x; acc.y += v.y; acc.z += v.z; acc.w += v.w;
        }
    }
    float inv = 1.0f / (float)(cnt > 0 ? cnt : 1);
    acc.x *= inv; acc.y *= inv; acc.z *= inv; acc.w *= inv;
    *(float4*)(g_mean + (size_t)node * FEAT + c4) = acc;
}

__device__ __forceinline__ float lrelu(float x) {
    return x > 0.f ? x : 0.01f * x;
}

// ---------------------------------------------------------------------------
// Kernel 3: fused dual GEMM (one layer):
//   out = lrelu(Xself @ Wl^T + bl) + (cnt>0 ? lrelu(Mean @ Wn^T + bn) : 0)
// BM=BN=64, BK=16, 256 threads, 4x4 register tile per branch.
// Both operands K-contiguous (NT gemm); tiles stored transposed in smem.
// ---------------------------------------------------------------------------
template <bool LAYER1>
__global__ __launch_bounds__(256) void dual_gemm_kernel(
    const float* __restrict__ Xext,
    const float* __restrict__ Wl, const float* __restrict__ bl,
    const float* __restrict__ Wn, const float* __restrict__ bn)
{
    constexpr int BM = 64, BN = 64, BK = 16, LDA = BM + 4;
    const float* __restrict__ Xs = LAYER1 ? Xext : (const float*)g_h1;
    const float* __restrict__ Ms = (const float*)g_mean;
    float* __restrict__ Out = LAYER1 ? g_h1 : g_h2;

    __shared__ __align__(16) float sX[BK][LDA];
    __shared__ __align__(16) float sM[BK][LDA];
    __shared__ __align__(16) float sL[BK][LDA];
    __shared__ __align__(16) float sN[BK][LDA];

    int t  = threadIdx.x;
    int tx = t & 15, ty = t >> 4;
    int m0 = blockIdx.y * BM, n0 = blockIdx.x * BN;
    int lr = t >> 2, lk = (t & 3) << 2;

    const float* px = Xs + (size_t)(m0 + lr) * FEAT + lk;
    const float* pm = Ms + (size_t)(m0 + lr) * FEAT + lk;
    const float* pl = Wl + (size_t)(n0 + lr) * FEAT + lk;
    const float* pn = Wn + (size_t)(n0 + lr) * FEAT + lk;

    float aL[4][4] = {}; float aN[4][4] = {};

    for (int k0 = 0; k0 < FEAT; k0 += BK) {
        float4 vx = *(const float4*)(px + k0);
        float4 vm = *(const float4*)(pm + k0);
        float4 vl = *(const float4*)(pl + k0);
        float4 vn = *(const float4*)(pn + k0);
        sX[lk+0][lr] = vx.x; sX[lk+1][lr] = vx.y; sX[lk+2][lr] = vx.z; sX[lk+3][lr] = vx.w;
        sM[lk+0][lr] = vm.x; sM[lk+1][lr] = vm.y; sM[lk+2][lr] = vm.z; sM[lk+3][lr] = vm.w;
        sL[lk+0][lr] = vl.x; sL[lk+1][lr] = vl.y; sL[lk+2][lr] = vl.z; sL[lk+3][lr] = vl.w;
        sN[lk+0][lr] = vn.x; sN[lk+1][lr] = vn.y; sN[lk+2][lr] = vn.z; sN[lk+3][lr] = vn.w;
        __syncthreads();
#pragma unroll
        for (int kk = 0; kk < BK; kk++) {
            float4 x4 = *(const float4*)&sX[kk][ty << 2];
            float4 m4 = *(const float4*)&sM[kk][ty << 2];
            float4 l4 = *(const float4*)&sL[kk][tx << 2];
            float4 n4 = *(const float4*)&sN[kk][tx << 2];
            float xa[4] = {x4.x, x4.y, x4.z, x4.w};
            float ma[4] = {m4.x, m4.y, m4.z, m4.w};
            float la[4] = {l4.x, l4.y, l4.z, l4.w};
            float na[4] = {n4.x, n4.y, n4.z, n4.w};
#pragma unroll
            for (int i = 0; i < 4; i++)
#pragma unroll
                for (int j = 0; j < 4; j++) {
                    aL[i][j] += xa[i] * la[j];
                    aN[i][j] += ma[i] * na[j];
                }
        }
        __syncthreads();
    }

#pragma unroll
    for (int i = 0; i < 4; i++) {
        int m = m0 + (ty << 2) + i;
        bool has = g_cnt[m] > 0;
        float4 o;
        float* op = &o.x;
#pragma unroll
        for (int j = 0; j < 4; j++) {
            int n = n0 + (tx << 2) + j;
            float xi = lrelu(aL[i][j] + __ldg(bl + n));
            float xj = lrelu(aN[i][j] + __ldg(bn + n));
            op[j] = has ? (xi + xj) : xi;
        }
        *(float4*)(Out + (size_t)m * FEAT + n0 + (tx << 2)) = o;
    }
}

// ---------------------------------------------------------------------------
// Kernel 4: final GEMM [8192,256]x[256,64] + fused row-wise log_softmax.
// BM=128 covers full C=64 per CTA, so softmax is done entirely in smem.
// ---------------------------------------------------------------------------
__global__ __launch_bounds__(256) void final_kernel(
    const float* __restrict__ W3, const float* __restrict__ b3,
    float* __restrict__ Out)
{
    constexpr int BM = 128, BK = 16;
    const float* __restrict__ H = (const float*)g_h2;

    __shared__ __align__(16) float sH[BK][BM + 4];
    __shared__ __align__(16) float sW[BK][64 + 4];
    __shared__ float sRes[BM][65];
    __shared__ float sLse[BM];

    int t  = threadIdx.x;
    int tx = t & 15, ty = t >> 4;
    int m0 = blockIdx.x * BM;
    int hr = t >> 1, hk = (t & 1) << 3;
    int wr = t >> 2, wk = (t & 3) << 2;

    float acc[8][4] = {};

    for (int k0 = 0; k0 < FEAT; k0 += BK) {
        float4 a0 = *(const float4*)(H  + (size_t)(m0 + hr) * FEAT + k0 + hk);
        float4 a1 = *(const float4*)(H  + (size_t)(m0 + hr) * FEAT + k0 + hk + 4);
        float4 w0 = *(const float4*)(W3 + (size_t)wr * FEAT + k0 + wk);
        sH[hk+0][hr] = a0.x; sH[hk+1][hr] = a0.y; sH[hk+2][hr] = a0.z; sH[hk+3][hr] = a0.w;
        sH[hk+4][hr] = a1.x; sH[hk+5][hr] = a1.y; sH[hk+6][hr] = a1.z; sH[hk+7][hr] = a1.w;
        sW[wk+0][wr] = w0.x; sW[wk+1][wr] = w0.y; sW[wk+2][wr] = w0.z; sW[wk+3][wr] = w0.w;
        __syncthreads();
#pragma unroll
        for (int kk = 0; kk < BK; kk++) {
            float4 h0 = *(const float4*)&sH[kk][ty << 3];
            float4 h1 = *(const float4*)&sH[kk][(ty << 3) + 4];
            float4 w4 = *(const float4*)&sW[kk][tx << 2];
            float ha[8] = {h0.x, h0.y, h0.z, h0.w, h1.x, h1.y, h1.z, h1.w};
            float wa[4] = {w4.x, w4.y, w4.z, w4.w};
#pragma unroll
            for (int i = 0; i < 8; i++)
#pragma unroll
                for (int j = 0; j < 4; j++)
                    acc[i][j] += ha[i] * wa[j];
        }
        __syncthreads();
    }

#pragma unroll
    for (int i = 0; i < 8; i++)
#pragma unroll
        for (int j = 0; j < 4; j++)
            sRes[(ty << 3) + i][(tx << 2) + j] = acc[i][j] + __ldg(b3 + (tx << 2) + j);
    __syncthreads();

    if (t < BM) {
        float mx = -1e30f;
#pragma unroll 8
        for (int c = 0; c < 64; c++) mx = fmaxf(mx, sRes[t][c]);
        float s = 0.f;
#pragma unroll 8
        for (int c = 0; c < 64; c++) s += expf(sRes[t][c] - mx);
        sLse[t] = mx + logf(s);
    }
    __syncthreads();

    for (int idx = t; idx < BM * 64; idx += 256) {
        int r = idx >> 6, c = idx & 63;
        Out[(size_t)(m0 + r) * 64 + c] = sRes[r][c] - sLse[r];
    }
}

// ---------------------------------------------------------------------------
extern "C" void kernel_launch(void* const* d_in, const int* in_sizes, int n_in,
                              void* d_out, int out_size) {
    const float* X   = (const float*)d_in[0];
    const int*   A   = (const int*)  d_in[1];
    const float* Wn1 = (const float*)d_in[2];
    const float* bn1 = (const float*)d_in[3];
    const float* Wl1 = (const float*)d_in[4];
    const float* bl1 = (const float*)d_in[5];
    const float* Wn2 = (const float*)d_in[6];
    const float* bn2 = (const float*)d_in[7];
    const float* Wl2 = (const float*)d_in[8];
    const float* bl2 = (const float*)d_in[9];
    const float* W3  = (const float*)d_in[10];
    const float* b3  = (const float*)d_in[11];
    float* out = (float*)d_out;

    // 1. neighbor lists (shared by both layers; k=10 list is prefix of k=25)
    nbr_kernel<<<N_NODES / 8, 256>>>(A);

    // 2. layer 1
    mean_kernel<K1, true><<<N_NODES / 4, 256>>>(X);
    dual_gemm_kernel<true><<<dim3(FEAT / 64, N_NODES / 64), 256>>>(X, Wl1, bl1, Wn1, bn1);

    // 3. layer 2
    mean_kernel<K2, false><<<N_NODES / 4, 256>>>(X);
    dual_gemm_kernel<false><<<dim3(FEAT / 64, N_NODES / 64), 256>>>(X, Wl2, bl2, Wn2, bn2);

    // 4. classifier + log_softmax
    final_kernel<<<N_NODES / 128, 256>>>(W3, b3, out);
}

// round 2
// speedup vs baseline: 1.2763x; 1.2763x over previous
#include <cuda_runtime.h>
#include <math.h>

#define N_NODES 8192
#define FEAT    256
#define K1      25
#define K2      10

// Scratch (device globals — no allocation allowed)
__device__ int   g_nbr[N_NODES * K1];
__device__ int   g_cnt[N_NODES];
__device__ float g_mean[N_NODES * FEAT];
__device__ float g_h1[N_NODES * FEAT];
__device__ float g_h2[N_NODES * FEAT];

// ---------------------------------------------------------------------------
// Kernel 1: first-K1 neighbor extraction. One warp per row, ballot prefix scan
// with early exit (A ~Bernoulli(0.5): typically 1-2 iterations of 32 cols).
// ---------------------------------------------------------------------------
__global__ void nbr_kernel(const int* __restrict__ A) {
    int warp = (blockIdx.x * blockDim.x + threadIdx.x) >> 5;
    int lane = threadIdx.x & 31;
    if (warp >= N_NODES) return;
    const int* row = A + (size_t)warp * N_NODES;
    int found = 0;
    for (int c = 0; c < N_NODES && found < K1; c += 32) {
        int v = __ldg(row + c + lane);
        unsigned m = __ballot_sync(0xffffffffu, v > 0);
        if (v > 0) {
            int r = found + __popc(m & ((1u << lane) - 1u));
            if (r < K1) g_nbr[warp * K1 + r] = c + lane;
        }
        found += __popc(m);
    }
    int cnt = found < K1 ? found : K1;
    if (lane < K1 && lane >= cnt) g_nbr[warp * K1 + lane] = 0;  // safe dummy
    if (lane == 0) g_cnt[warp] = cnt;
}

// ---------------------------------------------------------------------------
// Kernel 2: neighbor mean over first min(cnt, K) neighbors.
// 4 nodes per 256-thread block, float4 per thread, unrolled + predicated.
// ---------------------------------------------------------------------------
template <int K, bool FROM_X>
__global__ void mean_kernel(const float* __restrict__ X) {
    const float* __restrict__ In = FROM_X ? X : (const float*)g_h1;
    int node = blockIdx.x * 4 + (threadIdx.x >> 6);
    int c4   = (threadIdx.x & 63) << 2;
    int cnt = g_cnt[node]; if (cnt > K) cnt = K;
    const int* nb = g_nbr + node * K1;
    float4 acc = make_float4(0.f, 0.f, 0.f, 0.f);
#pragma unroll
    for (int t = 0; t < K; t++) {
        if (t < cnt) {
            float4 v = *(const float4*)(In + (size_t)nb[t] * FEAT + c4);
            acc.x += v.x; acc.y += v.y; acc.z += v.z; acc.w += v.w;
        }
    }
    float inv = 1.0f / (float)(cnt > 0 ? cnt : 1);
    acc.x *= inv; acc.y *= inv; acc.z *= inv; acc.w *= inv;
    *(float4*)(g_mean + (size_t)node * FEAT + c4) = acc;
}

__device__ __forceinline__ float lrelu(float x) {
    return x > 0.f ? x : 0.01f * x;
}

__device__ __forceinline__ unsigned f2tf(float x) {
    unsigned u;
    asm("cvt.rna.tf32.f32 %0, %1;" : "=r"(u) : "f"(x));
    return u;
}

__device__ __forceinline__ void mma_tf32(float* c,
    unsigned a0, unsigned a1, unsigned a2, unsigned a3,
    unsigned b0, unsigned b1)
{
    asm volatile(
        "mma.sync.aligned.m16n8k8.row.col.f32.tf32.tf32.f32 "
        "{%0,%1,%2,%3}, {%4,%5,%6,%7}, {%8,%9}, {%0,%1,%2,%3};"
        : "+f"(c[0]), "+f"(c[1]), "+f"(c[2]), "+f"(c[3])
        : "r"(a0), "r"(a1), "r"(a2), "r"(a3), "r"(b0), "r"(b1));
}

// ---------------------------------------------------------------------------
// Kernel 3: tf32 tensor-core GEMM, Out[m][n] over A[m][k] * W[n][k].
// MODE 0 (self):   Out = lrelu(A@W^T + b)
// MODE 1 (nbr):    Out += (cnt>0) ? lrelu(A@W^T + b) : 0   (RMW of self pass)
// BM=128 BN=64 BK=16, 8 warps (4x2), warp tile 32x32, double-buffered smem,
// XOR swizzle (col ^ ((k&3)<<3)) => conflict-free loads AND stores.
// ---------------------------------------------------------------------------
template<int MODE, int LAYER>
__global__ __launch_bounds__(256) void gemm_tf32(
    const float* __restrict__ Xext,
    const float* __restrict__ W, const float* __restrict__ bias)
{
    constexpr int BM = 128, BN = 64, BK = 16;
    const float* __restrict__ Ain =
        (LAYER == 1) ? (MODE == 0 ? Xext : (const float*)g_mean)
                     : (MODE == 0 ? (const float*)g_h1 : (const float*)g_mean);
    float* __restrict__ Out = (LAYER == 1) ? g_h1 : g_h2;

    __shared__ unsigned sA[2][BK][BM];
    __shared__ unsigned sB[2][BK][BN];

    int tid = threadIdx.x;
    int m0 = blockIdx.y * BM, n0 = blockIdx.x * BN;

    // loaders: A -> 8 floats/thread, B -> 4 floats/thread
    int am = tid & 127, ak = (tid >> 7) * 8;
    int bn = tid & 63,  bk = (tid >> 6) * 4;
    const float* pA = Ain + (size_t)(m0 + am) * FEAT + ak;
    const float* pB = W   + (size_t)(n0 + bn) * FEAT + bk;

    // fragment ids
    int warp = tid >> 5, lane = tid & 31;
    int wm = (warp >> 1) * 32, wn = (warp & 1) * 32;
    int group = lane >> 2, tig = lane & 3;
    int sw = tig << 3;

    float acc[2][4][4];
#pragma unroll
    for (int i = 0; i < 2; i++)
#pragma unroll
        for (int j = 0; j < 4; j++)
#pragma unroll
            for (int l = 0; l < 4; l++) acc[i][j][l] = 0.f;

#define STA(BUF, I, V) sA[BUF][ak + (I)][am ^ (((I) & 3) << 3)] = f2tf(V)
#define STB(BUF, I, V) sB[BUF][bk + (I)][bn ^ (((I) & 3) << 3)] = f2tf(V)

    { // prologue: tile 0
        float4 a0v = *(const float4*)(pA);
        float4 a1v = *(const float4*)(pA + 4);
        float4 bv  = *(const float4*)(pB);
        STA(0,0,a0v.x); STA(0,1,a0v.y); STA(0,2,a0v.z); STA(0,3,a0v.w);
        STA(0,4,a1v.x); STA(0,5,a1v.y); STA(0,6,a1v.z); STA(0,7,a1v.w);
        STB(0,0,bv.x);  STB(0,1,bv.y);  STB(0,2,bv.z);  STB(0,3,bv.w);
    }
    __syncthreads();

    int buf = 0;
    for (int k0 = BK; k0 <= FEAT; k0 += BK) {
        float4 na0, na1, nb;
        if (k0 < FEAT) {
            na0 = *(const float4*)(pA + k0);
            na1 = *(const float4*)(pA + k0 + 4);
            nb  = *(const float4*)(pB + k0);
        }
#pragma unroll
        for (int kk = 0; kk < BK; kk += 8) {
            int kA = kk + tig;
            unsigned af[2][4], bf[4][2];
#pragma unroll
            for (int mi = 0; mi < 2; mi++) {
                int r = wm + mi * 16 + group;
                af[mi][0] = sA[buf][kA    ][r       ^ sw];
                af[mi][1] = sA[buf][kA    ][(r + 8) ^ sw];
                af[mi][2] = sA[buf][kA + 4][r       ^ sw];
                af[mi][3] = sA[buf][kA + 4][(r + 8) ^ sw];
            }
#pragma unroll
            for (int ni = 0; ni < 4; ni++) {
                int c = (wn + ni * 8 + group) ^ sw;
                bf[ni][0] = sB[buf][kA    ][c];
                bf[ni][1] = sB[buf][kA + 4][c];
            }
#pragma unroll
            for (int mi = 0; mi < 2; mi++)
#pragma unroll
                for (int ni = 0; ni < 4; ni++)
                    mma_tf32(acc[mi][ni], af[mi][0], af[mi][1], af[mi][2], af[mi][3],
                             bf[ni][0], bf[ni][1]);
        }
        if (k0 < FEAT) {
            int b2 = buf ^ 1;
            STA(b2,0,na0.x); STA(b2,1,na0.y); STA(b2,2,na0.z); STA(b2,3,na0.w);
            STA(b2,4,na1.x); STA(b2,5,na1.y); STA(b2,6,na1.z); STA(b2,7,na1.w);
            STB(b2,0,nb.x);  STB(b2,1,nb.y);  STB(b2,2,nb.z);  STB(b2,3,nb.w);
            __syncthreads();
            buf = b2;
        }
    }

    // epilogue
#pragma unroll
    for (int mi = 0; mi < 2; mi++) {
#pragma unroll
        for (int half = 0; half < 2; half++) {
            int row = m0 + wm + mi * 16 + group + half * 8;
            bool has = true;
            if (MODE == 1) has = __ldg(&g_cnt[row]) > 0;
#pragma unroll
            for (int ni = 0; ni < 4; ni++) {
                int col = n0 + wn + ni * 8 + tig * 2;
                float v0 = lrelu(acc[mi][ni][half * 2 + 0] + __ldg(bias + col));
                float v1 = lrelu(acc[mi][ni][half * 2 + 1] + __ldg(bias + col + 1));
                float2* p = (float2*)(Out + (size_t)row * FEAT + col);
                if (MODE == 0) {
                    *p = make_float2(v0, v1);
                } else if (has) {
                    float2 o = *p; o.x += v0; o.y += v1; *p = o;
                }
            }
        }
    }
#undef STA
#undef STB
}

// ---------------------------------------------------------------------------
// Kernel 4: final GEMM [8192,256]x[256,64] (tf32 mma) + fused log_softmax.
// Single-buffered smem (48KB static limit with the 128x65 result tile).
// ---------------------------------------------------------------------------
__global__ __launch_bounds__(256) void final_kernel(
    const float* __restrict__ W3, const float* __restrict__ b3,
    float* __restrict__ OutP)
{
    constexpr int BM = 128, BN = 64, BK = 16;
    const float* __restrict__ H = (const float*)g_h2;

    __shared__ unsigned sA[BK][BM];
    __shared__ unsigned sB[BK][BN];
    __shared__ float sRes[BM][BN + 1];
    __shared__ float sLse[BM];

    int tid = threadIdx.x;
    int m0 = blockIdx.x * BM;
    int am = tid & 127, ak = (tid >> 7) * 8;
    int bn = tid & 63,  bk = (tid >> 6) * 4;
    const float* pA = H  + (size_t)(m0 + am) * FEAT + ak;
    const float* pB = W3 + (size_t)bn * FEAT + bk;

    int warp = tid >> 5, lane = tid & 31;
    int wm = (warp >> 1) * 32, wn = (warp & 1) * 32;
    int group = lane >> 2, tig = lane & 3;
    int sw = tig << 3;

    float acc[2][4][4];
#pragma unroll
    for (int i = 0; i < 2; i++)
#pragma unroll
        for (int j = 0; j < 4; j++)
#pragma unroll
            for (int l = 0; l < 4; l++) acc[i][j][l] = 0.f;

    for (int k0 = 0; k0 < FEAT; k0 += BK) {
        float4 a0v = *(const float4*)(pA + k0);
        float4 a1v = *(const float4*)(pA + k0 + 4);
        float4 bv  = *(const float4*)(pB + k0);
        __syncthreads();
        sA[ak + 0][am ^ 0 ] = f2tf(a0v.x); sA[ak + 1][am ^ 8 ] = f2tf(a0v.y);
        sA[ak + 2][am ^ 16] = f2tf(a0v.z); sA[ak + 3][am ^ 24] = f2tf(a0v.w);
        sA[ak + 4][am ^ 0 ] = f2tf(a1v.x); sA[ak + 5][am ^ 8 ] = f2tf(a1v.y);
        sA[ak + 6][am ^ 16] = f2tf(a1v.z); sA[ak + 7][am ^ 24] = f2tf(a1v.w);
        sB[bk + 0][bn ^ 0 ] = f2tf(bv.x);  sB[bk + 1][bn ^ 8 ] = f2tf(bv.y);
        sB[bk + 2][bn ^ 16] = f2tf(bv.z);  sB[bk + 3][bn ^ 24] = f2tf(bv.w);
        __syncthreads();
#pragma unroll
        for (int kk = 0; kk < BK; kk += 8) {
            int kA = kk + tig;
            unsigned af[2][4], bf[4][2];
#pragma unroll
            for (int mi = 0; mi < 2; mi++) {
                int r = wm + mi * 16 + group;
                af[mi][0] = sA[kA    ][r       ^ sw];
                af[mi][1] = sA[kA    ][(r + 8) ^ sw];
                af[mi][2] = sA[kA + 4][r       ^ sw];
                af[mi][3] = sA[kA + 4][(r + 8) ^ sw];
            }
#pragma unroll
            for (int ni = 0; ni < 4; ni++) {
                int c = (wn + ni * 8 + group) ^ sw;
                bf[ni][0] = sB[kA    ][c];
                bf[ni][1] = sB[kA + 4][c];
            }
#pragma unroll
            for (int mi = 0; mi < 2; mi++)
#pragma unroll
                for (int ni = 0; ni < 4; ni++)
                    mma_tf32(acc[mi][ni], af[mi][0], af[mi][1], af[mi][2], af[mi][3],
                             bf[ni][0], bf[ni][1]);
        }
    }

#pragma unroll
    for (int mi = 0; mi < 2; mi++)
#pragma unroll
        for (int half = 0; half < 2; half++) {
            int r = wm + mi * 16 + group + half * 8;
#pragma unroll
            for (int ni = 0; ni < 4; ni++) {
                int col = wn + ni * 8 + tig * 2;
                sRes[r][col]     = acc[mi][ni][half * 2 + 0] + __ldg(b3 + col);
                sRes[r][col + 1] = acc[mi][ni][half * 2 + 1] + __ldg(b3 + col + 1);
            }
        }
    __syncthreads();

    if (tid < BM) {
        float mx = -1e30f;
#pragma unroll 8
        for (int c = 0; c < 64; c++) mx = fmaxf(mx, sRes[tid][c]);
        float s = 0.f;
#pragma unroll 8
        for (int c = 0; c < 64; c++) s += expf(sRes[tid][c] - mx);
        sLse[tid] = mx + logf(s);
    }
    __syncthreads();

    for (int idx = tid; idx < BM * 64; idx += 256) {
        int r = idx >> 6, c = idx & 63;
        OutP[(size_t)(m0 + r) * 64 + c] = sRes[r][c] - sLse[r];
    }
}

// ---------------------------------------------------------------------------
extern "C" void kernel_launch(void* const* d_in, const int* in_sizes, int n_in,
                              void* d_out, int out_size) {
    const float* X   = (const float*)d_in[0];
    const int*   A   = (const int*)  d_in[1];
    const float* Wn1 = (const float*)d_in[2];
    const float* bn1 = (const float*)d_in[3];
    const float* Wl1 = (const float*)d_in[4];
    const float* bl1 = (const float*)d_in[5];
    const float* Wn2 = (const float*)d_in[6];
    const float* bn2 = (const float*)d_in[7];
    const float* Wl2 = (const float*)d_in[8];
    const float* bl2 = (const float*)d_in[9];
    const float* W3  = (const float*)d_in[10];
    const float* b3  = (const float*)d_in[11];
    float* out = (float*)d_out;

    dim3 ggrid(FEAT / 64, N_NODES / 128);

    // neighbor lists (k=10 list is a prefix of the k=25 list)
    nbr_kernel<<<N_NODES / 8, 256>>>(A);

    // layer 1
    mean_kernel<K1, true><<<N_NODES / 4, 256>>>(X);
    gemm_tf32<0, 1><<<ggrid, 256>>>(X, Wl1, bl1);   // self -> g_h1
    gemm_tf32<1, 1><<<ggrid, 256>>>(X, Wn1, bn1);   // neighbor += -> g_h1

    // layer 2
    mean_kernel<K2, false><<<N_NODES / 4, 256>>>(X);
    gemm_tf32<0, 2><<<ggrid, 256>>>(X, Wl2, bl2);   // self -> g_h2
    gemm_tf32<1, 2><<<ggrid, 256>>>(X, Wn2, bn2);   // neighbor += -> g_h2

    // classifier + log_softmax
    final_kernel<<<N_NODES / 128, 256>>>(W3, b3, out);
}

// round 3
// speedup vs baseline: 1.9014x; 1.4897x over previous
#include <cuda_runtime.h>
#include <math.h>

#define N_NODES 8192
#define FEAT    256
#define K1      25
#define K2      10

// Scratch (device globals — no allocation allowed)
__device__ int   g_nbr[N_NODES * K1];
__device__ int   g_cnt[N_NODES];
__device__ float g_mean[N_NODES * FEAT];
__device__ float g_h1[N_NODES * FEAT];   // combined layer-1 output
__device__ float g_s[N_NODES * FEAT];    // self-branch output (per layer, reused)
__device__ float g_n[N_NODES * FEAT];    // nbr-branch output (masked; reused)

// ---------------------------------------------------------------------------
// Kernel 1: first-K1 neighbor extraction. One warp per row, ballot prefix scan
// with early exit (A ~Bernoulli(0.5): typically 1-2 iterations of 32 cols).
// ---------------------------------------------------------------------------
__global__ void nbr_kernel(const int* __restrict__ A) {
    int warp = (blockIdx.x * blockDim.x + threadIdx.x) >> 5;
    int lane = threadIdx.x & 31;
    if (warp >= N_NODES) return;
    const int* row = A + (size_t)warp * N_NODES;
    int found = 0;
    for (int c = 0; c < N_NODES && found < K1; c += 32) {
        int v = __ldg(row + c + lane);
        unsigned m = __ballot_sync(0xffffffffu, v > 0);
        if (v > 0) {
            int r = found + __popc(m & ((1u << lane) - 1u));
            if (r < K1) g_nbr[warp * K1 + r] = c + lane;
        }
        found += __popc(m);
    }
    int cnt = found < K1 ? found : K1;
    if (lane < K1 && lane >= cnt) g_nbr[warp * K1 + lane] = 0;  // safe dummy
    if (lane == 0) g_cnt[warp] = cnt;
}

// ---------------------------------------------------------------------------
// Kernel 2: neighbor mean over first min(cnt, K) neighbors.
// ---------------------------------------------------------------------------
template <int K, bool FROM_X>
__global__ void mean_kernel(const float* __restrict__ X) {
    const float* __restrict__ In = FROM_X ? X : (const float*)g_h1;
    int node = blockIdx.x * 4 + (threadIdx.x >> 6);
    int c4   = (threadIdx.x & 63) << 2;
    int cnt = g_cnt[node]; if (cnt > K) cnt = K;
    const int* nb = g_nbr + node * K1;
    float4 acc = make_float4(0.f, 0.f, 0.f, 0.f);
#pragma unroll
    for (int t = 0; t < K; t++) {
        if (t < cnt) {
            float4 v = *(const float4*)(In + (size_t)nb[t] * FEAT + c4);
            acc.x += v.x; acc.y += v.y; acc.z += v.z; acc.w += v.w;
        }
    }
    float inv = 1.0f / (float)(cnt > 0 ? cnt : 1);
    acc.x *= inv; acc.y *= inv; acc.z *= inv; acc.w *= inv;
    *(float4*)(g_mean + (size_t)node * FEAT + c4) = acc;
}

__device__ __forceinline__ float lrelu(float x) {
    return x > 0.f ? x : 0.01f * x;
}

__device__ __forceinline__ unsigned f2tf(float x) {
    unsigned u;
    asm("cvt.rna.tf32.f32 %0, %1;" : "=r"(u) : "f"(x));
    return u;
}

__device__ __forceinline__ void mma_tf32(float* c,
    unsigned a0, unsigned a1, unsigned a2, unsigned a3,
    unsigned b0, unsigned b1)
{
    asm volatile(
        "mma.sync.aligned.m16n8k8.row.col.f32.tf32.tf32.f32 "
        "{%0,%1,%2,%3}, {%4,%5,%6,%7}, {%8,%9}, {%0,%1,%2,%3};"
        : "+f"(c[0]), "+f"(c[1]), "+f"(c[2]), "+f"(c[3])
        : "r"(a0), "r"(a1), "r"(a2), "r"(a3), "r"(b0), "r"(b1));
}

__device__ __forceinline__ void cp16(unsigned dst, const void* src) {
    asm volatile("cp.async.cg.shared.global [%0], [%1], 16;" :: "r"(dst), "l"(src));
}
__device__ __forceinline__ void cp_commit() {
    asm volatile("cp.async.commit_group;" ::: "memory");
}
__device__ __forceinline__ void cp_wait0() {
    asm volatile("cp.async.wait_group 0;" ::: "memory");
}

// ---------------------------------------------------------------------------
// Kernel 3: M-stacked dual GEMM (one layer).
//   blockIdx.y <  64 : self branch, A = Xself, W = Wl  -> g_s = lrelu(.)
//   blockIdx.y >= 64 : nbr  branch, A = Mean,  W = Wn  -> g_n = mask*lrelu(.)
// BM=128 BN=64 BK=32, 8 warps (4x2), warp tile 32x32, cp.async double buffer.
// smem layout: row-major [m][k] with 16B-chunk XOR swizzle (chunk ^ (row&7)).
// Raw f32 fed to tf32 mma (hardware truncation).
// ---------------------------------------------------------------------------
template<int LAYER>
__global__ __launch_bounds__(256) void gemm_dual(
    const float* __restrict__ X,
    const float* __restrict__ Wl, const float* __restrict__ bl,
    const float* __restrict__ Wn, const float* __restrict__ bn)
{
    constexpr int BM = 128, BN = 64, BK = 32, NIT = FEAT / BK;
    __shared__ unsigned sA[2][BM * BK];
    __shared__ unsigned sB[2][BN * BK];

    int tid = threadIdx.x;
    bool self = blockIdx.y < 64;
    int mt = self ? blockIdx.y : blockIdx.y - 64;
    int m0 = mt * BM, n0 = blockIdx.x * BN;

    const float* Abase = self ? (LAYER == 1 ? X : (const float*)g_h1)
                              : (const float*)g_mean;
    const float* W    = self ? Wl : Wn;
    const float* bias = self ? bl : bn;
    float* Out        = self ? g_s : g_n;

    // loader mapping: A 4 chunks/thread, B 2 chunks/thread (16B chunks)
    int am  = tid >> 1, akc = (tid & 1) * 4;
    int bn_ = tid >> 2, bkc = (tid & 3) * 2;
    const float* pA = Abase + (size_t)(m0 + am)  * FEAT + akc * 4;
    const float* pB = W     + (size_t)(n0 + bn_) * FEAT + bkc * 4;
    unsigned baseA = (unsigned)__cvta_generic_to_shared(&sA[0][0]);
    unsigned baseB = (unsigned)__cvta_generic_to_shared(&sB[0][0]);
    unsigned dA = baseA + am  * (BK * 4);
    unsigned dB = baseB + bn_ * (BK * 4);
    int aswz = am  & 7, bswz = bn_ & 7;

    // fragment ids
    int warp = tid >> 5, lane = tid & 31;
    int wm = (warp >> 1) * 32, wn = (warp & 1) * 32;
    int group = lane >> 2, tig = lane & 3;

    float acc[2][4][4];
#pragma unroll
    for (int i = 0; i < 2; i++)
#pragma unroll
        for (int j = 0; j < 4; j++)
#pragma unroll
            for (int l = 0; l < 4; l++) acc[i][j][l] = 0.f;

#define ISSUE(st, k0)                                                          \
    {                                                                          \
        unsigned oa = dA + (st) * (BM * BK * 4);                               \
        const float* ga = pA + (k0);                                           \
        _Pragma("unroll")                                                      \
        for (int j = 0; j < 4; j++)                                            \
            cp16(oa + (((akc + j) ^ aswz) << 4), ga + j * 4);                  \
        unsigned ob = dB + (st) * (BN * BK * 4);                               \
        const float* gb = pB + (k0);                                           \
        _Pragma("unroll")                                                      \
        for (int j = 0; j < 2; j++)                                            \
            cp16(ob + (((bkc + j) ^ bswz) << 4), gb + j * 4);                  \
        cp_commit();                                                           \
    }

#define LDA(st, m, k) sA[st][(m) * BK + (((((k) >> 2) ^ ((m) & 7)) << 2) | ((k) & 3))]
#define LDB(st, n, k) sB[st][(n) * BK + (((((k) >> 2) ^ ((n) & 7)) << 2) | ((k) & 3))]

    ISSUE(0, 0);

    int st = 0;
    for (int it = 0; it < NIT; it++) {
        cp_wait0();
        __syncthreads();
        if (it + 1 < NIT) ISSUE(st ^ 1, (it + 1) * BK);
#pragma unroll
        for (int kk = 0; kk < BK; kk += 8) {
            int ka = kk + tig;
            unsigned af[2][4], bf[4][2];
#pragma unroll
            for (int mi = 0; mi < 2; mi++) {
                int r = wm + mi * 16 + group;
                af[mi][0] = LDA(st, r,     ka);
                af[mi][1] = LDA(st, r + 8, ka);
                af[mi][2] = LDA(st, r,     ka + 4);
                af[mi][3] = LDA(st, r + 8, ka + 4);
            }
#pragma unroll
            for (int ni = 0; ni < 4; ni++) {
                int n = wn + ni * 8 + group;
                bf[ni][0] = LDB(st, n, ka);
                bf[ni][1] = LDB(st, n, ka + 4);
            }
#pragma unroll
            for (int mi = 0; mi < 2; mi++)
#pragma unroll
                for (int ni = 0; ni < 4; ni++)
                    mma_tf32(acc[mi][ni], af[mi][0], af[mi][1], af[mi][2], af[mi][3],
                             bf[ni][0], bf[ni][1]);
        }
        st ^= 1;
    }

    // epilogue
#pragma unroll
    for (int mi = 0; mi < 2; mi++) {
#pragma unroll
        for (int half = 0; half < 2; half++) {
            int row = m0 + wm + mi * 16 + group + half * 8;
            bool has = self ? true : (__ldg(&g_cnt[row]) > 0);
#pragma unroll
            for (int ni = 0; ni < 4; ni++) {
                int col = n0 + wn + ni * 8 + tig * 2;
                float v0 = lrelu(acc[mi][ni][half * 2 + 0] + __ldg(bias + col));
                float v1 = lrelu(acc[mi][ni][half * 2 + 1] + __ldg(bias + col + 1));
                if (!has) { v0 = 0.f; v1 = 0.f; }
                *(float2*)(Out + (size_t)row * FEAT + col) = make_float2(v0, v1);
            }
        }
    }
#undef ISSUE
#undef LDA
#undef LDB
}

// ---------------------------------------------------------------------------
// Kernel: combine h1 = s + n (mask already applied to n)
// ---------------------------------------------------------------------------
__global__ void combine_kernel() {
    int i = blockIdx.x * 256 + threadIdx.x;
    float4 a = ((const float4*)g_s)[i];
    float4 b = ((const float4*)g_n)[i];
    a.x += b.x; a.y += b.y; a.z += b.z; a.w += b.w;
    ((float4*)g_h1)[i] = a;
}

// ---------------------------------------------------------------------------
// Kernel 4: final GEMM [8192,256]x[256,64] (tf32 mma) + fused log_softmax.
// Loader combines h2 = g_s + g_n on the fly.
// ---------------------------------------------------------------------------
__global__ __launch_bounds__(256) void final_kernel(
    const float* __restrict__ W3, const float* __restrict__ b3,
    float* __restrict__ OutP)
{
    constexpr int BM = 128, BN = 64, BK = 16;

    __shared__ unsigned sA[BK][BM];
    __shared__ unsigned sB[BK][BN];
    __shared__ float sRes[BM][BN + 1];
    __shared__ float sLse[BM];

    int tid = threadIdx.x;
    int m0 = blockIdx.x * BM;
    int am = tid & 127, ak = (tid >> 7) * 8;
    int bn = tid & 63,  bk = (tid >> 6) * 4;
    const float* pS = g_s + (size_t)(m0 + am) * FEAT + ak;
    const float* pN = g_n + (size_t)(m0 + am) * FEAT + ak;
    const float* pB = W3  + (size_t)bn * FEAT + bk;

    int warp = tid >> 5, lane = tid & 31;
    int wm = (warp >> 1) * 32, wn = (warp & 1) * 32;
    int group = lane >> 2, tig = lane & 3;
    int sw = tig << 3;

    float acc[2][4][4];
#pragma unroll
    for (int i = 0; i < 2; i++)
#pragma unroll
        for (int j = 0; j < 4; j++)
#pragma unroll
            for (int l = 0; l < 4; l++) acc[i][j][l] = 0.f;

    for (int k0 = 0; k0 < FEAT; k0 += BK) {
        float4 s0 = *(const float4*)(pS + k0);
        float4 s1 = *(const float4*)(pS + k0 + 4);
        float4 q0 = *(const float4*)(pN + k0);
        float4 q1 = *(const float4*)(pN + k0 + 4);
        float4 bv = *(const float4*)(pB + k0);
        float4 a0v = make_float4(s0.x + q0.x, s0.y + q0.y, s0.z + q0.z, s0.w + q0.w);
        float4 a1v = make_float4(s1.x + q1.x, s1.y + q1.y, s1.z + q1.z, s1.w + q1.w);
        __syncthreads();
        sA[ak + 0][am ^ 0 ] = f2tf(a0v.x); sA[ak + 1][am ^ 8 ] = f2tf(a0v.y);
        sA[ak + 2][am ^ 16] = f2tf(a0v.z); sA[ak + 3][am ^ 24] = f2tf(a0v.w);
        sA[ak + 4][am ^ 0 ] = f2tf(a1v.x); sA[ak + 5][am ^ 8 ] = f2tf(a1v.y);
        sA[ak + 6][am ^ 16] = f2tf(a1v.z); sA[ak + 7][am ^ 24] = f2tf(a1v.w);
        sB[bk + 0][bn ^ 0 ] = f2tf(bv.x);  sB[bk + 1][bn ^ 8 ] = f2tf(bv.y);
        sB[bk + 2][bn ^ 16] = f2tf(bv.z);  sB[bk + 3][bn ^ 24] = f2tf(bv.w);
        __syncthreads();
#pragma unroll
        for (int kk = 0; kk < BK; kk += 8) {
            int kA = kk + tig;
            unsigned af[2][4], bf[4][2];
#pragma unroll
            for (int mi = 0; mi < 2; mi++) {
                int r = wm + mi * 16 + group;
                af[mi][0] = sA[kA    ][r       ^ sw];
                af[mi][1] = sA[kA    ][(r + 8) ^ sw];
                af[mi][2] = sA[kA + 4][r       ^ sw];
                af[mi][3] = sA[kA + 4][(r + 8) ^ sw];
            }
#pragma unroll
            for (int ni = 0; ni < 4; ni++) {
                int c = (wn + ni * 8 + group) ^ sw;
                bf[ni][0] = sB[kA    ][c];
                bf[ni][1] = sB[kA + 4][c];
            }
#pragma unroll
            for (int mi = 0; mi < 2; mi++)
#pragma unroll
                for (int ni = 0; ni < 4; ni++)
                    mma_tf32(acc[mi][ni], af[mi][0], af[mi][1], af[mi][2], af[mi][3],
                             bf[ni][0], bf[ni][1]);
        }
    }

#pragma unroll
    for (int mi = 0; mi < 2; mi++)
#pragma unroll
        for (int half = 0; half < 2; half++) {
            int r = wm + mi * 16 + group + half * 8;
#pragma unroll
            for (int ni = 0; ni < 4; ni++) {
                int col = wn + ni * 8 + tig * 2;
                sRes[r][col]     = acc[mi][ni][half * 2 + 0] + __ldg(b3 + col);
                sRes[r][col + 1] = acc[mi][ni][half * 2 + 1] + __ldg(b3 + col + 1);
            }
        }
    __syncthreads();

    if (tid < BM) {
        float mx = -1e30f;
#pragma unroll 8
        for (int c = 0; c < 64; c++) mx = fmaxf(mx, sRes[tid][c]);
        float s = 0.f;
#pragma unroll 8
        for (int c = 0; c < 64; c++) s += expf(sRes[tid][c] - mx);
        sLse[tid] = mx + logf(s);
    }
    __syncthreads();

    for (int idx = tid; idx < BM * 64; idx += 256) {
        int r = idx >> 6, c = idx & 63;
        OutP[(size_t)(m0 + r) * 64 + c] = sRes[r][c] - sLse[r];
    }
}

// ---------------------------------------------------------------------------
extern "C" void kernel_launch(void* const* d_in, const int* in_sizes, int n_in,
                              void* d_out, int out_size) {
    const float* X   = (const float*)d_in[0];
    const int*   A   = (const int*)  d_in[1];
    const float* Wn1 = (const float*)d_in[2];
    const float* bn1 = (const float*)d_in[3];
    const float* Wl1 = (const float*)d_in[4];
    const float* bl1 = (const float*)d_in[5];
    const float* Wn2 = (const float*)d_in[6];
    const float* bn2 = (const float*)d_in[7];
    const float* Wl2 = (const float*)d_in[8];
    const float* bl2 = (const float*)d_in[9];
    const float* W3  = (const float*)d_in[10];
    const float* b3  = (const float*)d_in[11];
    float* out = (float*)d_out;

    dim3 ggrid(FEAT / 64, 2 * N_NODES / 128);   // (4, 128) = 512 CTAs

    nbr_kernel<<<N_NODES / 8, 256>>>(A);

    // layer 1
    mean_kernel<K1, true><<<N_NODES / 4, 256>>>(X);
    gemm_dual<1><<<ggrid, 256>>>(X, Wl1, bl1, Wn1, bn1);
    combine_kernel<<<N_NODES * FEAT / 4 / 256, 256>>>();

    // layer 2
    mean_kernel<K2, false><<<N_NODES / 4, 256>>>(X);
    gemm_dual<2><<<ggrid, 256>>>(X, Wl2, bl2, Wn2, bn2);

    // classifier + log_softmax
    final_kernel<<<N_NODES / 128, 256>>>(W3, b3, out);
}

// round 4
// speedup vs baseline: 2.0874x; 1.0978x over previous
#include <cuda_runtime.h>
#include <math.h>

#define N_NODES 8192
#define FEAT    256
#define K1      25
#define K2      10

// Scratch (device globals — no allocation allowed)
__device__ int   g_nbr[N_NODES * K1];
__device__ int   g_cnt[N_NODES];
__device__ float g_s [N_NODES * FEAT];   // self branch:  lrelu(A@Wl^T + bl)
__device__ float g_yn[N_NODES * FEAT];   // raw nbr GEMM: A@Wn^T
__device__ float g_h1[N_NODES * FEAT];   // layer-1 output
__device__ float g_h2[N_NODES * FEAT];   // layer-2 output

// ---------------------------------------------------------------------------
// Kernel 1: first-K1 neighbor extraction. One warp per row, ballot prefix scan
// with early exit (A ~Bernoulli(0.5): typically 1-2 iterations of 32 cols).
// ---------------------------------------------------------------------------
__global__ void nbr_kernel(const int* __restrict__ A) {
    int warp = (blockIdx.x * blockDim.x + threadIdx.x) >> 5;
    int lane = threadIdx.x & 31;
    if (warp >= N_NODES) return;
    const int* row = A + (size_t)warp * N_NODES;
    int found = 0;
    for (int c = 0; c < N_NODES && found < K1; c += 32) {
        int v = __ldg(row + c + lane);
        unsigned m = __ballot_sync(0xffffffffu, v > 0);
        if (v > 0) {
            int r = found + __popc(m & ((1u << lane) - 1u));
            if (r < K1) g_nbr[warp * K1 + r] = c + lane;
        }
        found += __popc(m);
    }
    int cnt = found < K1 ? found : K1;
    if (lane < K1 && lane >= cnt) g_nbr[warp * K1 + lane] = 0;  // safe dummy
    if (lane == 0) g_cnt[warp] = cnt;
}

__device__ __forceinline__ float lrelu(float x) {
    return x > 0.f ? x : 0.01f * x;
}

__device__ __forceinline__ unsigned f2tf(float x) {
    unsigned u;
    asm("cvt.rna.tf32.f32 %0, %1;" : "=r"(u) : "f"(x));
    return u;
}

__device__ __forceinline__ void mma_tf32(float* c,
    unsigned a0, unsigned a1, unsigned a2, unsigned a3,
    unsigned b0, unsigned b1)
{
    asm volatile(
        "mma.sync.aligned.m16n8k8.row.col.f32.tf32.tf32.f32 "
        "{%0,%1,%2,%3}, {%4,%5,%6,%7}, {%8,%9}, {%0,%1,%2,%3};"
        : "+f"(c[0]), "+f"(c[1]), "+f"(c[2]), "+f"(c[3])
        : "r"(a0), "r"(a1), "r"(a2), "r"(a3), "r"(b0), "r"(b1));
}

__device__ __forceinline__ void cp16(unsigned dst, const void* src) {
    asm volatile("cp.async.cg.shared.global [%0], [%1], 16;" :: "r"(dst), "l"(src));
}
__device__ __forceinline__ void cp_commit() {
    asm volatile("cp.async.commit_group;" ::: "memory");
}
__device__ __forceinline__ void cp_wait0() {
    asm volatile("cp.async.wait_group 0;" ::: "memory");
}

// ---------------------------------------------------------------------------
// Kernel 2: N-concatenated dual GEMM (one layer), both halves read the SAME A.
//   blockIdx.x < 4 : self half, W = Wl -> g_s  = lrelu(A@Wl^T + bl)
//   blockIdx.x >= 4: nbr  half, W = Wn -> g_yn = A@Wn^T          (raw)
// BM=128 BN=64 BK=32, 8 warps (4x2), warp tile 32x32, cp.async double buffer.
// smem: [m][k] with 16B-chunk XOR swizzle (chunk ^ (row&7)).
// ---------------------------------------------------------------------------
template<int LAYER>
__global__ __launch_bounds__(256) void gemm_dual(
    const float* __restrict__ X,
    const float* __restrict__ Wl, const float* __restrict__ bl,
    const float* __restrict__ Wn)
{
    constexpr int BM = 128, BN = 64, BK = 32, NIT = FEAT / BK;
    __shared__ unsigned sA[2][BM * BK];
    __shared__ unsigned sB[2][BN * BK];

    int tid = threadIdx.x;
    bool self = blockIdx.x < 4;
    int n0 = (blockIdx.x & 3) * BN;
    int m0 = blockIdx.y * BM;

    const float* Abase = (LAYER == 1) ? X : (const float*)g_h1;
    const float* W     = self ? Wl : Wn;
    float* Out         = self ? g_s : g_yn;

    // loader mapping: A 4 chunks/thread, B 2 chunks/thread (16B chunks)
    int am  = tid >> 1, akc = (tid & 1) * 4;
    int bn_ = tid >> 2, bkc = (tid & 3) * 2;
    const float* pA = Abase + (size_t)(m0 + am)  * FEAT + akc * 4;
    const float* pB = W     + (size_t)(n0 + bn_) * FEAT + bkc * 4;
    unsigned baseA = (unsigned)__cvta_generic_to_shared(&sA[0][0]);
    unsigned baseB = (unsigned)__cvta_generic_to_shared(&sB[0][0]);
    unsigned dA = baseA + am  * (BK * 4);
    unsigned dB = baseB + bn_ * (BK * 4);
    int aswz = am  & 7, bswz = bn_ & 7;

    // fragment ids
    int warp = tid >> 5, lane = tid & 31;
    int wm = (warp >> 1) * 32, wn = (warp & 1) * 32;
    int group = lane >> 2, tig = lane & 3;

    float acc[2][4][4];
#pragma unroll
    for (int i = 0; i < 2; i++)
#pragma unroll
        for (int j = 0; j < 4; j++)
#pragma unroll
            for (int l = 0; l < 4; l++) acc[i][j][l] = 0.f;

#define ISSUE(st, k0)                                                          \
    {                                                                          \
        unsigned oa = dA + (st) * (BM * BK * 4);                               \
        const float* ga = pA + (k0);                                           \
        _Pragma("unroll")                                                      \
        for (int j = 0; j < 4; j++)                                            \
            cp16(oa + (((akc + j) ^ aswz) << 4), ga + j * 4);                  \
        unsigned ob = dB + (st) * (BN * BK * 4);                               \
        const float* gb = pB + (k0);                                           \
        _Pragma("unroll")                                                      \
        for (int j = 0; j < 2; j++)                                            \
            cp16(ob + (((bkc + j) ^ bswz) << 4), gb + j * 4);                  \
        cp_commit();                                                           \
    }

#define LDA(st, m, k) sA[st][(m) * BK + (((((k) >> 2) ^ ((m) & 7)) << 2) | ((k) & 3))]
#define LDB(st, n, k) sB[st][(n) * BK + (((((k) >> 2) ^ ((n) & 7)) << 2) | ((k) & 3))]

    ISSUE(0, 0);

    int st = 0;
    for (int it = 0; it < NIT; it++) {
        cp_wait0();
        __syncthreads();
        if (it + 1 < NIT) ISSUE(st ^ 1, (it + 1) * BK);
#pragma unroll
        for (int kk = 0; kk < BK; kk += 8) {
            int ka = kk + tig;
            unsigned af[2][4], bf[4][2];
#pragma unroll
            for (int mi = 0; mi < 2; mi++) {
                int r = wm + mi * 16 + group;
                af[mi][0] = LDA(st, r,     ka);
                af[mi][1] = LDA(st, r + 8, ka);
                af[mi][2] = LDA(st, r,     ka + 4);
                af[mi][3] = LDA(st, r + 8, ka + 4);
            }
#pragma unroll
            for (int ni = 0; ni < 4; ni++) {
                int n = wn + ni * 8 + group;
                bf[ni][0] = LDB(st, n, ka);
                bf[ni][1] = LDB(st, n, ka + 4);
            }
#pragma unroll
            for (int mi = 0; mi < 2; mi++)
#pragma unroll
                for (int ni = 0; ni < 4; ni++)
                    mma_tf32(acc[mi][ni], af[mi][0], af[mi][1], af[mi][2], af[mi][3],
                             bf[ni][0], bf[ni][1]);
        }
        st ^= 1;
    }

    // epilogue: self half gets bias+lrelu, yn half is raw
#pragma unroll
    for (int mi = 0; mi < 2; mi++) {
#pragma unroll
        for (int half = 0; half < 2; half++) {
            int row = m0 + wm + mi * 16 + group + half * 8;
#pragma unroll
            for (int ni = 0; ni < 4; ni++) {
                int col = n0 + wn + ni * 8 + tig * 2;
                float v0 = acc[mi][ni][half * 2 + 0];
                float v1 = acc[mi][ni][half * 2 + 1];
                if (self) {
                    v0 = lrelu(v0 + __ldg(bl + col));
                    v1 = lrelu(v1 + __ldg(bl + col + 1));
                }
                *(float2*)(Out + (size_t)row * FEAT + col) = make_float2(v0, v1);
            }
        }
    }
#undef ISSUE
#undef LDA
#undef LDB
}

// ---------------------------------------------------------------------------
// Kernel 3: gather-mean over first min(cnt,K) rows of g_yn + bias + lrelu,
// combined with the self branch:  h = g_s + (cnt>0 ? lrelu(mean + bn) : 0).
// 4 nodes / 256-thread block, float4/thread, dual accumulators for ILP.
// Neighbor indices loaded unconditionally (dummy slots are 0 -> safe).
// ---------------------------------------------------------------------------
template <int K>
__global__ __launch_bounds__(256) void comb_kernel(
    const float* __restrict__ bn, float* __restrict__ OutH)
{
    int node = blockIdx.x * 4 + (threadIdx.x >> 6);
    int c4   = (threadIdx.x & 63) << 2;
    int cnt = g_cnt[node]; if (cnt > K) cnt = K;
    const int* nb = g_nbr + node * K1;

    int idx[K];
#pragma unroll
    for (int t = 0; t < K; t++) idx[t] = __ldg(nb + t);

    float4 a0 = make_float4(0.f, 0.f, 0.f, 0.f);
    float4 a1 = make_float4(0.f, 0.f, 0.f, 0.f);
#pragma unroll
    for (int t = 0; t < K; t += 2) {
        if (t < cnt) {
            float4 v = *(const float4*)(g_yn + (size_t)idx[t] * FEAT + c4);
            a0.x += v.x; a0.y += v.y; a0.z += v.z; a0.w += v.w;
        }
        if (t + 1 < cnt) {
            float4 v = *(const float4*)(g_yn + (size_t)idx[t + 1] * FEAT + c4);
            a1.x += v.x; a1.y += v.y; a1.z += v.z; a1.w += v.w;
        }
    }
    float inv = (cnt > 0) ? (1.0f / (float)cnt) : 0.f;   // inv=0 also kills xj
    float4 b4 = *(const float4*)(bn + c4);
    float4 s4 = *(const float4*)(g_s + (size_t)node * FEAT + c4);
    float4 o;
    if (cnt > 0) {
        o.x = s4.x + lrelu((a0.x + a1.x) * inv + b4.x);
        o.y = s4.y + lrelu((a0.y + a1.y) * inv + b4.y);
        o.z = s4.z + lrelu((a0.z + a1.z) * inv + b4.z);
        o.w = s4.w + lrelu((a0.w + a1.w) * inv + b4.w);
    } else {
        o = s4;
    }
    *(float4*)(OutH + (size_t)node * FEAT + c4) = o;
}

// ---------------------------------------------------------------------------
// Kernel 4: final GEMM [8192,256]x[256,64] (tf32 mma) + fused log_softmax.
// ---------------------------------------------------------------------------
__global__ __launch_bounds__(256) void final_kernel(
    const float* __restrict__ W3, const float* __restrict__ b3,
    float* __restrict__ OutP)
{
    constexpr int BM = 128, BN = 64, BK = 16;
    const float* __restrict__ H = (const float*)g_h2;

    __shared__ unsigned sA[BK][BM];
    __shared__ unsigned sB[BK][BN];
    __shared__ float sRes[BM][BN + 1];
    __shared__ float sLse[BM];

    int tid = threadIdx.x;
    int m0 = blockIdx.x * BM;
    int am = tid & 127, ak = (tid >> 7) * 8;
    int bn = tid & 63,  bk = (tid >> 6) * 4;
    const float* pA = H  + (size_t)(m0 + am) * FEAT + ak;
    const float* pB = W3 + (size_t)bn * FEAT + bk;

    int warp = tid >> 5, lane = tid & 31;
    int wm = (warp >> 1) * 32, wn = (warp & 1) * 32;
    int group = lane >> 2, tig = lane & 3;
    int sw = tig << 3;

    float acc[2][4][4];
#pragma unroll
    for (int i = 0; i < 2; i++)
#pragma unroll
        for (int j = 0; j < 4; j++)
#pragma unroll
            for (int l = 0; l < 4; l++) acc[i][j][l] = 0.f;

    for (int k0 = 0; k0 < FEAT; k0 += BK) {
        float4 a0v = *(const float4*)(pA + k0);
        float4 a1v = *(const float4*)(pA + k0 + 4);
        float4 bv  = *(const float4*)(pB + k0);
        __syncthreads();
        sA[ak + 0][am ^ 0 ] = f2tf(a0v.x); sA[ak + 1][am ^ 8 ] = f2tf(a0v.y);
        sA[ak + 2][am ^ 16] = f2tf(a0v.z); sA[ak + 3][am ^ 24] = f2tf(a0v.w);
        sA[ak + 4][am ^ 0 ] = f2tf(a1v.x); sA[ak + 5][am ^ 8 ] = f2tf(a1v.y);
        sA[ak + 6][am ^ 16] = f2tf(a1v.z); sA[ak + 7][am ^ 24] = f2tf(a1v.w);
        sB[bk + 0][bn ^ 0 ] = f2tf(bv.x);  sB[bk + 1][bn ^ 8 ] = f2tf(bv.y);
        sB[bk + 2][bn ^ 16] = f2tf(bv.z);  sB[bk + 3][bn ^ 24] = f2tf(bv.w);
        __syncthreads();
#pragma unroll
        for (int kk = 0; kk < BK; kk += 8) {
            int kA = kk + tig;
            unsigned af[2][4], bf[4][2];
#pragma unroll
            for (int mi = 0; mi < 2; mi++) {
                int r = wm + mi * 16 + group;
                af[mi][0] = sA[kA    ][r       ^ sw];
                af[mi][1] = sA[kA    ][(r + 8) ^ sw];
                af[mi][2] = sA[kA + 4][r       ^ sw];
                af[mi][3] = sA[kA + 4][(r + 8) ^ sw];
            }
#pragma unroll
            for (int ni = 0; ni < 4; ni++) {
                int c = (wn + ni * 8 + group) ^ sw;
                bf[ni][0] = sB[kA    ][c];
                bf[ni][1] = sB[kA + 4][c];
            }
#pragma unroll
            for (int mi = 0; mi < 2; mi++)
#pragma unroll
                for (int ni = 0; ni < 4; ni++)
                    mma_tf32(acc[mi][ni], af[mi][0], af[mi][1], af[mi][2], af[mi][3],
                             bf[ni][0], bf[ni][1]);
        }
    }

#pragma unroll
    for (int mi = 0; mi < 2; mi++)
#pragma unroll
        for (int half = 0; half < 2; half++) {
            int r = wm + mi * 16 + group + half * 8;
#pragma unroll
            for (int ni = 0; ni < 4; ni++) {
                int col = wn + ni * 8 + tig * 2;
                sRes[r][col]     = acc[mi][ni][half * 2 + 0] + __ldg(b3 + col);
                sRes[r][col + 1] = acc[mi][ni][half * 2 + 1] + __ldg(b3 + col + 1);
            }
        }
    __syncthreads();

    if (tid < BM) {
        float mx = -1e30f;
#pragma unroll 8
        for (int c = 0; c < 64; c++) mx = fmaxf(mx, sRes[tid][c]);
        float s = 0.f;
#pragma unroll 8
        for (int c = 0; c < 64; c++) s += expf(sRes[tid][c] - mx);
        sLse[tid] = mx + logf(s);
    }
    __syncthreads();

    for (int idx = tid; idx < BM * 64; idx += 256) {
        int r = idx >> 6, c = idx & 63;
        OutP[(size_t)(m0 + r) * 64 + c] = sRes[r][c] - sLse[r];
    }
}

// ---------------------------------------------------------------------------
extern "C" void kernel_launch(void* const* d_in, const int* in_sizes, int n_in,
                              void* d_out, int out_size) {
    const float* X   = (const float*)d_in[0];
    const int*   A   = (const int*)  d_in[1];
    const float* Wn1 = (const float*)d_in[2];
    const float* bn1 = (const float*)d_in[3];
    const float* Wl1 = (const float*)d_in[4];
    const float* bl1 = (const float*)d_in[5];
    const float* Wn2 = (const float*)d_in[6];
    const float* bn2 = (const float*)d_in[7];
    const float* Wl2 = (const float*)d_in[8];
    const float* bl2 = (const float*)d_in[9];
    const float* W3  = (const float*)d_in[10];
    const float* b3  = (const float*)d_in[11];
    float* out = (float*)d_out;

    dim3 ggrid(8, N_NODES / 128);   // 8 n-tiles (4 self + 4 yn) x 64 m-tiles

    float* h1p; cudaGetSymbolAddress((void**)&h1p, g_h1);
    float* h2p; cudaGetSymbolAddress((void**)&h2p, g_h2);

    // layer 1 GEMM depends only on X -> launch first
    gemm_dual<1><<<ggrid, 256>>>(X, Wl1, bl1, Wn1);
    nbr_kernel<<<N_NODES / 8, 256>>>(A);
    comb_kernel<K1><<<N_NODES / 4, 256>>>(bn1, h1p);

    // layer 2
    gemm_dual<2><<<ggrid, 256>>>(X, Wl2, bl2, Wn2);
    comb_kernel<K2><<<N_NODES / 4, 256>>>(bn2, h2p);

    // classifier + log_softmax
    final_kernel<<<N_NODES / 128, 256>>>(W3, b3, out);
}